// round 11
// baseline (speedup 1.0000x reference)
#include <cuda_runtime.h>
#include <cuda_fp16.h>
#include <cstdint>

#define B_  8
#define N_  1024
#define D_  768
#define H_  12
#define HD_ 64
#define M_  (B_*N_)      // 8192
#define C3_ (3*D_)       // 2304
#define SCLOG2E 0.1803368801111204f   // 0.125 * log2(e)

// ------------------------- scratch (__device__ globals) --------------------
__device__ __half g_cf[(size_t)M_*D_];           // attention output (fp16)

__device__ __half g_qf[(size_t)B_*H_*N_*HD_];    // Q fp16 (pre-scaled)
__device__ __half g_kf[(size_t)B_*H_*N_*HD_];    // K fp16
__device__ __half g_vf[(size_t)B_*H_*N_*HD_];    // V fp16

__device__ __half g_xf[(size_t)M_*D_];           // x   (fp16)
__device__ __half g_wf[(size_t)C3_*D_];          // W_qkv^T  [2304][768] fp16
__device__ __half g_wpf[(size_t)D_*D_];          // W_proj^T [768][768]  fp16

// ------------------------- helpers -----------------------------------------
__device__ __forceinline__ uint32_t smem_u32(const void* p) {
    uint32_t a;
    asm("{ .reg .u64 t; cvta.to.shared.u64 t, %1; cvt.u32.u64 %0, t; }"
        : "=r"(a) : "l"(p));
    return a;
}
#define SWZ64(o)  ((o) ^ (((o) >> 3) & 0x30))
#define SWZ128(o) ((o) ^ (((o) >> 3) & 0x70))

#define CP16(s, g)  asm volatile("cp.async.cg.shared.global [%0], [%1], 16;" :: "r"(s), "l"(g))
#define CPCOMMIT()  asm volatile("cp.async.commit_group;" ::: "memory")
#define CPWAIT(n)   asm volatile("cp.async.wait_group %0;" :: "n"(n) : "memory")

__device__ __forceinline__ void ldsm_x4(uint32_t addr, uint32_t& r0, uint32_t& r1,
                                        uint32_t& r2, uint32_t& r3) {
    asm volatile("ldmatrix.sync.aligned.m8n8.x4.shared.b16 {%0,%1,%2,%3}, [%4];"
                 : "=r"(r0), "=r"(r1), "=r"(r2), "=r"(r3) : "r"(addr));
}
__device__ __forceinline__ void ldsm_x4t(uint32_t addr, uint32_t& r0, uint32_t& r1,
                                         uint32_t& r2, uint32_t& r3) {
    asm volatile("ldmatrix.sync.aligned.m8n8.x4.trans.shared.b16 {%0,%1,%2,%3}, [%4];"
                 : "=r"(r0), "=r"(r1), "=r"(r2), "=r"(r3) : "r"(addr));
}
__device__ __forceinline__ void mma16816h(float* d, const uint32_t* a, const uint32_t* b) {
    asm volatile(
        "mma.sync.aligned.m16n8k16.row.col.f32.f16.f16.f32 "
        "{%0,%1,%2,%3}, {%4,%5,%6,%7}, {%8,%9}, {%0,%1,%2,%3};"
        : "+f"(d[0]), "+f"(d[1]), "+f"(d[2]), "+f"(d[3])
        : "r"(a[0]), "r"(a[1]), "r"(a[2]), "r"(a[3]), "r"(b[0]), "r"(b[1]));
}
__device__ __forceinline__ float ex2f(float x) {
    float y;
    asm("ex2.approx.f32 %0, %1;" : "=f"(y) : "f"(x));
    return y;
}
__device__ __forceinline__ uint32_t packhf(float lo, float hi) {
    uint32_t r;
    asm("cvt.rn.f16x2.f32 %0, %1, %2;" : "=r"(r) : "f"(hi), "f"(lo));
    return r;
}

// ------------------------- conversion kernels ------------------------------
__global__ void cvt_x_kernel(const float* __restrict__ in) {
    int i = blockIdx.x * 256 + threadIdx.x;           // float4 index
    if (i < (M_ * D_) / 4) {
        float4 v = ((const float4*)in)[i];
        ((__half2*)g_xf)[i * 2]     = __floats2half2_rn(v.x, v.y);
        ((__half2*)g_xf)[i * 2 + 1] = __floats2half2_rn(v.z, v.w);
    }
}
template<int WHICH>
__global__ void cvtT_kernel(const float* __restrict__ W) {
    constexpr int K = D_;
    constexpr int N = (WHICH == 0) ? C3_ : D_;
    __half* dst = (WHICH == 0) ? g_wf : g_wpf;
    __shared__ float tile[32][33];
    const int nb = blockIdx.x * 32, kb = blockIdx.y * 32;
    const int tx = threadIdx.x, ty = threadIdx.y;
    #pragma unroll
    for (int r = ty; r < 32; r += 8)
        tile[r][tx] = W[(size_t)(kb + r) * N + nb + tx];
    __syncthreads();
    #pragma unroll
    for (int r = ty; r < 32; r += 8) {
        const int n = nb + r, k = kb + tx;
        dst[(size_t)n * K + k] = __float2half_rn(tile[tx][r]);
    }
}

// ------------------------- fp16 HMMA GEMM, 128x256 CTA / 64x64 warp ---------
// 256 threads, 8 warps (2 M-halves x 4 N-quarters). 4-stage cp.async ring.
#define KSTEP_    32
#define NSTEPS_   (D_ / KSTEP_)    // 24
#define A_TILE_B  8192             // 128 rows * 64 bytes
#define B_TILE_B  16384            // 256 rows * 64 bytes
#define STAGE_B   (A_TILE_B + B_TILE_B)   // 24 KB
#define NSTAGE_G  4
#define SMEM_GEMM (NSTAGE_G * STAGE_B)    // 96 KB

template<int MODE>
__global__ __launch_bounds__(256, 1)
void mma_gemm(const float* __restrict__ bias, float* __restrict__ Cout)
{
    extern __shared__ __align__(1024) char smem[];
    const int tid = threadIdx.x, lane = tid & 31, wid = tid >> 5;
    const int m0 = blockIdx.y * 128, n0 = blockIdx.x * 256;
    const int wm = wid & 1;        // 0..1 -> 64 M-rows
    const int wn = wid >> 1;       // 0..3 -> 64 N-cols

    const __half* __restrict__ Af = (MODE == 0) ? g_xf : g_cf;
    const __half* __restrict__ Bf = (MODE == 0) ? g_wf : g_wpf;

    // load mapping: A = 512 16B-chunks (2/thread), B = 1024 (4/thread)
    uint32_t sAo[2], sBo[4];
    int rA[2], cA[2], rB[4], cB[4];
    #pragma unroll
    for (int j = 0; j < 2; j++) {
        const int ca = j * 256 + tid;
        rA[j] = ca >> 2; cA[j] = ca & 3;
        sAo[j] = SWZ64((uint32_t)(rA[j] * 64 + cA[j] * 16));
    }
    #pragma unroll
    for (int j = 0; j < 4; j++) {
        const int cb = j * 256 + tid;
        rB[j] = cb >> 2; cB[j] = cb & 3;
        sBo[j] = SWZ64((uint32_t)(rB[j] * 64 + cB[j] * 16));
    }
    const uint32_t sbase = smem_u32(smem);

    const uint32_t aoff = SWZ64((uint32_t)((wm * 64 + (lane & 15)) * 64 + (lane >> 4) * 16));
    const uint32_t boff = SWZ64((uint32_t)((wn * 64 + (lane & 7) + ((lane & 16) ? 8 : 0)) * 64
                                           + ((lane >> 3) & 1) * 16));

    float acc[4][8][4];
    #pragma unroll
    for (int i = 0; i < 4; i++)
        #pragma unroll
        for (int j = 0; j < 8; j++)
            #pragma unroll
            for (int e = 0; e < 4; e++) acc[i][j][e] = 0.0f;

    auto load_step = [&](int s, int st) {
        const int kt = s * KSTEP_;
        const uint32_t d = sbase + st * STAGE_B;
        #pragma unroll
        for (int j = 0; j < 2; j++)
            CP16(d + sAo[j], Af + (size_t)(m0 + rA[j]) * D_ + kt + cA[j] * 8);
        #pragma unroll
        for (int j = 0; j < 4; j++)
            CP16(d + A_TILE_B + sBo[j], Bf + (size_t)(n0 + rB[j]) * D_ + kt + cB[j] * 8);
        CPCOMMIT();
    };

    load_step(0, 0);
    load_step(1, 1);
    load_step(2, 2);
    CPWAIT(2);
    __syncthreads();

    #pragma unroll 1
    for (int s = 0; s < NSTEPS_; s++) {
        if (s + 3 < NSTEPS_) load_step(s + 3, (s + 3) & 3);

        const uint32_t tb = sbase + (s & 3) * STAGE_B;
        #pragma unroll
        for (int kk = 0; kk < 2; kk++) {
            const uint32_t kx = kk ? 32u : 0u;
            uint32_t ah[4][4];
            #pragma unroll
            for (int mi = 0; mi < 4; mi++)
                ldsm_x4((tb + mi * 1024) + (aoff ^ kx),
                        ah[mi][0], ah[mi][1], ah[mi][2], ah[mi][3]);
            uint32_t bh[8][2];
            #pragma unroll
            for (int nb = 0; nb < 4; nb++)
                ldsm_x4((tb + A_TILE_B + nb * 1024) + (boff ^ kx),
                        bh[nb*2][0], bh[nb*2][1], bh[nb*2+1][0], bh[nb*2+1][1]);
            #pragma unroll
            for (int mi = 0; mi < 4; mi++)
                #pragma unroll
                for (int ni = 0; ni < 8; ni++)
                    mma16816h(acc[mi][ni], ah[mi], bh[ni]);
        }

        if (s + 3 < NSTEPS_)      { CPWAIT(2); }
        else if (s + 2 < NSTEPS_) { CPWAIT(1); }
        else if (s + 1 < NSTEPS_) { CPWAIT(0); }
        if (s + 1 < NSTEPS_) __syncthreads();
    }

    // ---- epilogue -----------------------------------------------------------
    #pragma unroll
    for (int mi = 0; mi < 4; mi++) {
        #pragma unroll
        for (int ni = 0; ni < 8; ni++) {
            const int cc = n0 + wn * 64 + ni * 8 + (lane & 3) * 2;
            const float b0v = bias[cc], b1v = bias[cc + 1];
            #pragma unroll
            for (int half = 0; half < 2; half++) {
                const int m = m0 + wm * 64 + mi * 16 + (lane >> 2) + half * 8;
                float v0 = acc[mi][ni][half * 2 + 0] + b0v;
                float v1 = acc[mi][ni][half * 2 + 1] + b1v;
                if (MODE == 0) {
                    const int bb = m >> 10, n = m & 1023;
                    const int trip = cc / D_;
                    const int rem = cc - trip * D_;
                    const int h = rem >> 6, d = rem & 63;
                    size_t off = ((((size_t)bb * H_ + h) * N_) + n) * HD_ + d;
                    const float sc = (trip == 0) ? SCLOG2E : 1.0f;
                    __half* dst = (trip == 0) ? g_qf : (trip == 1) ? g_kf : g_vf;
                    *(__half2*)(dst + off) = __floats2half2_rn(v0 * sc, v1 * sc);
                } else {
                    *(float2*)&Cout[(size_t)m * D_ + cc] = make_float2(v0, v1);
                }
            }
        }
    }
}

// ------------------------- HMMA flash attention (R9 structure) ---------------
#define ATT_Q_B   16384                 // Q: 128*128B
#define ATT_ST_B  16384                 // Kf + Vf: 2 * 64*128B
#define NSTAGE_A  4
#define SMEM_ATTN (ATT_Q_B + NSTAGE_A * ATT_ST_B)   // 80 KB

__global__ __launch_bounds__(256, 1)
void attn_mma()
{
    extern __shared__ __align__(1024) char sm[];
    const uint32_t sb = smem_u32(sm);
    const int tid = threadIdx.x, lane = tid & 31, wid = tid >> 5;
    const int bh = blockIdx.y, q0 = blockIdx.x * 128;
    const size_t bo = (size_t)bh * N_ * HD_;

    const __half* __restrict__ Qf = g_qf + bo + (size_t)q0 * HD_;
    const __half* __restrict__ Kf = g_kf + bo;
    const __half* __restrict__ Vf = g_vf + bo;

    // Q tile: 128 rows x 128 B
    #pragma unroll
    for (int j = 0; j < 4; j++) {
        const int id = j * 256 + tid;
        const int r  = id >> 3;
        const int c  = id & 7;
        CP16(sb + SWZ128((uint32_t)(r * 128 + c * 16)), Qf + (size_t)r * HD_ + c * 8);
    }
    CPCOMMIT();

    auto load_kv = [&](int it, int st) {
        const int kt = it * 64;
        #pragma unroll
        for (int j = 0; j < 4; j++) {
            const int id = (j & 1) * 256 + tid;
            const int t  = j >> 1;               // 0:Kf 1:Vf
            const int r  = id >> 3;
            const int c  = id & 7;
            const __half* src = ((t == 0) ? Kf : Vf) + (size_t)(kt + r) * HD_ + c * 8;
            CP16(sb + ATT_Q_B + st * ATT_ST_B + t * 8192 +
                 SWZ128((uint32_t)(r * 128 + c * 16)), src);
        }
        CPCOMMIT();
    };
    load_kv(0, 0);
    load_kv(1, 1);
    load_kv(2, 2);

    CPWAIT(2);             // Q + KV0 ready
    __syncthreads();

    uint32_t qh[4][4];
    const int arow = wid * 16 + (lane & 15);
    #pragma unroll
    for (int kc = 0; kc < 4; kc++) {
        const uint32_t off = SWZ128((uint32_t)(arow * 128 + (kc * 2 + (lane >> 4)) * 16));
        ldsm_x4(sb + off, qh[kc][0], qh[kc][1], qh[kc][2], qh[kc][3]);
    }

    float o[8][4];
    #pragma unroll
    for (int i = 0; i < 8; i++)
        #pragma unroll
        for (int e = 0; e < 4; e++) o[i][e] = 0.0f;
    float m0r = -1e30f, m1r = -1e30f, l0r = 0.0f, l1r = 0.0f;

    const int krow = (lane & 7) + ((lane >> 4) & 1) * 8;
    const int kchk = (lane >> 3) & 1;
    const int vrow = lane & 15;
    const int vchk = lane >> 4;

    #pragma unroll 1
    for (int it = 0; it < 16; it++) {
        if (it + 3 < 16) load_kv(it + 3, (it + 3) & 3);

        const uint32_t kb = sb + ATT_Q_B + (it & 3) * ATT_ST_B;

        // ---- S = Q K^T (single-pass fp16) --------------------------------------
        float s[8][4];
        #pragma unroll
        for (int i = 0; i < 8; i++)
            #pragma unroll
            for (int e = 0; e < 4; e++) s[i][e] = 0.0f;

        #pragma unroll
        for (int kc = 0; kc < 4; kc++) {
            #pragma unroll
            for (int p = 0; p < 4; p++) {
                const uint32_t off =
                    SWZ128((uint32_t)((p * 16 + krow) * 128 + (kc * 2 + kchk) * 16));
                uint32_t h0, h1, h2, h3;
                ldsm_x4(kb + off, h0, h1, h2, h3);
                uint32_t bh0[2] = {h0, h1}, bh1[2] = {h2, h3};
                mma16816h(s[2*p],     qh[kc], bh0);
                mma16816h(s[2*p + 1], qh[kc], bh1);
            }
        }

        // ---- online softmax ---------------------------------------------------
        float t0 = -1e30f, t1 = -1e30f;
        #pragma unroll
        for (int nt = 0; nt < 8; nt++) {
            t0 = fmaxf(t0, fmaxf(s[nt][0], s[nt][1]));
            t1 = fmaxf(t1, fmaxf(s[nt][2], s[nt][3]));
        }
        t0 = fmaxf(t0, __shfl_xor_sync(0xffffffffu, t0, 1));
        t0 = fmaxf(t0, __shfl_xor_sync(0xffffffffu, t0, 2));
        t1 = fmaxf(t1, __shfl_xor_sync(0xffffffffu, t1, 1));
        t1 = fmaxf(t1, __shfl_xor_sync(0xffffffffu, t1, 2));
        const float mn0 = fmaxf(m0r, t0), mn1 = fmaxf(m1r, t1);
        const float cr0 = ex2f(m0r - mn0), cr1 = ex2f(m1r - mn1);
        m0r = mn0; m1r = mn1;
        l0r *= cr0; l1r *= cr1;
        #pragma unroll
        for (int nt = 0; nt < 8; nt++) {
            o[nt][0] *= cr0; o[nt][1] *= cr0;
            o[nt][2] *= cr1; o[nt][3] *= cr1;
        }
        float ps0 = 0.0f, ps1 = 0.0f;
        #pragma unroll
        for (int nt = 0; nt < 8; nt++) {
            s[nt][0] = ex2f(s[nt][0] - mn0);
            s[nt][1] = ex2f(s[nt][1] - mn0);
            s[nt][2] = ex2f(s[nt][2] - mn1);
            s[nt][3] = ex2f(s[nt][3] - mn1);
            ps0 += s[nt][0] + s[nt][1];
            ps1 += s[nt][2] + s[nt][3];
        }
        l0r += ps0; l1r += ps1;

        // ---- P -> fp16 A-fragments ----------------------------------------------
        uint32_t aph[4][4];
        #pragma unroll
        for (int kc = 0; kc < 4; kc++) {
            #pragma unroll
            for (int g = 0; g < 4; g++) {
                const int nt = 2 * kc + (g >> 1);
                aph[kc][g] = packhf(s[nt][(g & 1) * 2 + 0], s[nt][(g & 1) * 2 + 1]);
            }
        }

        // ---- O += P V (single-pass fp16) ----------------------------------------
        #pragma unroll
        for (int kc = 0; kc < 4; kc++) {
            #pragma unroll
            for (int pr = 0; pr < 4; pr++) {
                const uint32_t off =
                    SWZ128((uint32_t)((kc * 16 + vrow) * 128 + (pr * 2 + vchk) * 16));
                uint32_t h0, h1, h2, h3;
                ldsm_x4t(kb + 8192 + off, h0, h1, h2, h3);
                uint32_t vh0[2] = {h0, h1}, vh1[2] = {h2, h3};
                mma16816h(o[2*pr],     aph[kc], vh0);
                mma16816h(o[2*pr + 1], aph[kc], vh1);
            }
        }

        if (it + 3 < 16)      { CPWAIT(2); }
        else if (it + 2 < 16) { CPWAIT(1); }
        else if (it + 1 < 16) { CPWAIT(0); }
        if (it + 1 < 16) __syncthreads();
    }

    // ---- finalize: write fp16 ctx directly ------------------------------------
    l0r += __shfl_xor_sync(0xffffffffu, l0r, 1);
    l0r += __shfl_xor_sync(0xffffffffu, l0r, 2);
    l1r += __shfl_xor_sync(0xffffffffu, l1r, 1);
    l1r += __shfl_xor_sync(0xffffffffu, l1r, 2);
    const float inv0 = 1.0f / l0r, inv1 = 1.0f / l1r;

    const int b = bh / H_, h = bh - b * H_;
    const int row0 = q0 + wid * 16 + (lane >> 2);
    __half* out0 = g_cf + ((size_t)(b * N_ + row0)) * D_ + h * HD_ + (lane & 3) * 2;
    __half* out1 = out0 + (size_t)8 * D_;
    #pragma unroll
    for (int nt = 0; nt < 8; nt++) {
        *(__half2*)(out0 + nt * 8) = __floats2half2_rn(o[nt][0] * inv0, o[nt][1] * inv0);
        *(__half2*)(out1 + nt * 8) = __floats2half2_rn(o[nt][2] * inv1, o[nt][3] * inv1);
    }
}

// ---------------------------------------------------------------------------
extern "C" void kernel_launch(void* const* d_in, const int* in_sizes, int n_in,
                              void* d_out, int out_size)
{
    const float* x     = (const float*)d_in[0];
    const float* Wqkv  = (const float*)d_in[1];
    const float* bqkv  = (const float*)d_in[2];
    const float* Wproj = (const float*)d_in[3];
    const float* bproj = (const float*)d_in[4];
    float* out = (float*)d_out;

    cudaFuncSetAttribute(mma_gemm<0>, cudaFuncAttributeMaxDynamicSharedMemorySize, SMEM_GEMM);
    cudaFuncSetAttribute(mma_gemm<1>, cudaFuncAttributeMaxDynamicSharedMemorySize, SMEM_GEMM);
    cudaFuncSetAttribute(attn_mma,    cudaFuncAttributeMaxDynamicSharedMemorySize, SMEM_ATTN);

    cvt_x_kernel<<<(M_ * D_ / 4 + 255) / 256, 256>>>(x);
    cvtT_kernel<0><<<dim3(C3_ / 32, D_ / 32), dim3(32, 8)>>>(Wqkv);
    cvtT_kernel<1><<<dim3(D_ / 32, D_ / 32), dim3(32, 8)>>>(Wproj);

    // QKV GEMM (fp16, 128x256 CTA, 8 warps) -> Q (pre-scaled), K, V fp16
    mma_gemm<0><<<dim3(C3_ / 256, M_ / 128), 256, SMEM_GEMM>>>(bqkv, nullptr);

    // flash attention (R9 structure): fp16 S + PV -> fp16 ctx
    attn_mma<<<dim3(N_ / 128, B_ * H_), 256, SMEM_ATTN>>>();

    // output projection (fp16)
    mma_gemm<1><<<dim3(D_ / 256, M_ / 128), 256, SMEM_GEMM>>>(bproj, out);
}

// round 12
// speedup vs baseline: 1.2727x; 1.2727x over previous
#include <cuda_runtime.h>
#include <cuda_fp16.h>
#include <cstdint>

#define B_  8
#define N_  1024
#define D_  768
#define H_  12
#define HD_ 64
#define M_  (B_*N_)      // 8192
#define C3_ (3*D_)       // 2304
#define SCLOG2E 0.1803368801111204f   // 0.125 * log2(e)

// ------------------------- scratch (__device__ globals) --------------------
__device__ __half g_cf[(size_t)M_*D_];           // attention output (fp16)

__device__ __half g_qf[(size_t)B_*H_*N_*HD_];    // Q fp16 (pre-scaled)
__device__ __half g_kf[(size_t)B_*H_*N_*HD_];    // K fp16
__device__ __half g_vf[(size_t)B_*H_*N_*HD_];    // V fp16

__device__ __half g_xf[(size_t)M_*D_];           // x   (fp16)
__device__ __half g_wf[(size_t)C3_*D_];          // W_qkv^T  [2304][768] fp16
__device__ __half g_wpf[(size_t)D_*D_];          // W_proj^T [768][768]  fp16

// ------------------------- helpers -----------------------------------------
__device__ __forceinline__ uint32_t smem_u32(const void* p) {
    uint32_t a;
    asm("{ .reg .u64 t; cvta.to.shared.u64 t, %1; cvt.u32.u64 %0, t; }"
        : "=r"(a) : "l"(p));
    return a;
}
#define SWZ64(o)  ((o) ^ (((o) >> 3) & 0x30))
#define SWZ128(o) ((o) ^ (((o) >> 3) & 0x70))

#define CP16(s, g)  asm volatile("cp.async.cg.shared.global [%0], [%1], 16;" :: "r"(s), "l"(g))
#define CPCOMMIT()  asm volatile("cp.async.commit_group;" ::: "memory")
#define CPWAIT(n)   asm volatile("cp.async.wait_group %0;" :: "n"(n) : "memory")

__device__ __forceinline__ void ldsm_x4(uint32_t addr, uint32_t& r0, uint32_t& r1,
                                        uint32_t& r2, uint32_t& r3) {
    asm volatile("ldmatrix.sync.aligned.m8n8.x4.shared.b16 {%0,%1,%2,%3}, [%4];"
                 : "=r"(r0), "=r"(r1), "=r"(r2), "=r"(r3) : "r"(addr));
}
__device__ __forceinline__ void ldsm_x4t(uint32_t addr, uint32_t& r0, uint32_t& r1,
                                         uint32_t& r2, uint32_t& r3) {
    asm volatile("ldmatrix.sync.aligned.m8n8.x4.trans.shared.b16 {%0,%1,%2,%3}, [%4];"
                 : "=r"(r0), "=r"(r1), "=r"(r2), "=r"(r3) : "r"(addr));
}
__device__ __forceinline__ void mma16816h(float* d, const uint32_t* a, const uint32_t* b) {
    asm volatile(
        "mma.sync.aligned.m16n8k16.row.col.f32.f16.f16.f32 "
        "{%0,%1,%2,%3}, {%4,%5,%6,%7}, {%8,%9}, {%0,%1,%2,%3};"
        : "+f"(d[0]), "+f"(d[1]), "+f"(d[2]), "+f"(d[3])
        : "r"(a[0]), "r"(a[1]), "r"(a[2]), "r"(a[3]), "r"(b[0]), "r"(b[1]));
}
__device__ __forceinline__ float ex2f(float x) {
    float y;
    asm("ex2.approx.f32 %0, %1;" : "=f"(y) : "f"(x));
    return y;
}
__device__ __forceinline__ uint32_t packhf(float lo, float hi) {
    uint32_t r;
    asm("cvt.rn.f16x2.f32 %0, %1, %2;" : "=r"(r) : "f"(hi), "f"(lo));
    return r;
}

// ------------------------- conversion kernels ------------------------------
__global__ void cvt_x_kernel(const float* __restrict__ in) {
    int i = blockIdx.x * 256 + threadIdx.x;           // float4 index
    if (i < (M_ * D_) / 4) {
        float4 v = ((const float4*)in)[i];
        ((__half2*)g_xf)[i * 2]     = __floats2half2_rn(v.x, v.y);
        ((__half2*)g_xf)[i * 2 + 1] = __floats2half2_rn(v.z, v.w);
    }
}
template<int WHICH>
__global__ void cvtT_kernel(const float* __restrict__ W) {
    constexpr int K = D_;
    constexpr int N = (WHICH == 0) ? C3_ : D_;
    __half* dst = (WHICH == 0) ? g_wf : g_wpf;
    __shared__ float tile[32][33];
    const int nb = blockIdx.x * 32, kb = blockIdx.y * 32;
    const int tx = threadIdx.x, ty = threadIdx.y;
    #pragma unroll
    for (int r = ty; r < 32; r += 8)
        tile[r][tx] = W[(size_t)(kb + r) * N + nb + tx];
    __syncthreads();
    #pragma unroll
    for (int r = ty; r < 32; r += 8) {
        const int n = nb + r, k = kb + tx;
        dst[(size_t)n * K + k] = __float2half_rn(tile[tx][r]);
    }
}

// ------------------------- fp16 HMMA GEMM, 64x64 warp tiles (R9) -------------
#define KSTEP_    32
#define NSTEPS_   (D_ / KSTEP_)    // 24
#define TILE_B    8192             // 128 rows * 64 bytes (fp16 128x32)
#define BUF_B     (2 * TILE_B)     // A, B  (16 KB / stage)
#define NSTAGE_G  4
#define SMEM_GEMM (NSTAGE_G * BUF_B)   // 64 KB

template<int MODE>
__global__ __launch_bounds__(128, 2)
void mma_gemm(const float* __restrict__ bias, float* __restrict__ Cout)
{
    extern __shared__ __align__(1024) char smem[];
    const int tid = threadIdx.x, lane = tid & 31, wid = tid >> 5;
    const int m0 = blockIdx.y * 128, n0 = blockIdx.x * 128;
    const int wm = wid & 1;
    const int wn = wid >> 1;

    const __half* __restrict__ Af = (MODE == 0) ? g_xf : g_cf;
    const __half* __restrict__ Bf = (MODE == 0) ? g_wf : g_wpf;

    const int lr = tid >> 2, lc = tid & 3;
    uint32_t sAo[4];
    #pragma unroll
    for (int j = 0; j < 4; j++)
        sAo[j] = SWZ64((uint32_t)((j * 32 + lr) * 64 + lc * 16));
    const uint32_t sbase = smem_u32(smem);

    const uint32_t aoff = SWZ64((uint32_t)((wm * 64 + (lane & 15)) * 64 + (lane >> 4) * 16));
    const uint32_t boff = SWZ64((uint32_t)((wn * 64 + (lane & 7) + ((lane & 16) ? 8 : 0)) * 64
                                           + ((lane >> 3) & 1) * 16));

    float acc[4][8][4];
    #pragma unroll
    for (int i = 0; i < 4; i++)
        #pragma unroll
        for (int j = 0; j < 8; j++)
            #pragma unroll
            for (int e = 0; e < 4; e++) acc[i][j][e] = 0.0f;

    auto load_step = [&](int s, int st) {
        const int kt = s * KSTEP_;
        const uint32_t d = sbase + st * BUF_B;
        #pragma unroll
        for (int j = 0; j < 4; j++)
            CP16(d + 0 * TILE_B + sAo[j], Af + (size_t)(m0 + j * 32 + lr) * D_ + kt + lc * 8);
        #pragma unroll
        for (int j = 0; j < 4; j++)
            CP16(d + 1 * TILE_B + sAo[j], Bf + (size_t)(n0 + j * 32 + lr) * D_ + kt + lc * 8);
        CPCOMMIT();
    };

    load_step(0, 0);
    load_step(1, 1);
    load_step(2, 2);
    CPWAIT(2);
    __syncthreads();

    #pragma unroll 1
    for (int s = 0; s < NSTEPS_; s++) {
        if (s + 3 < NSTEPS_) load_step(s + 3, (s + 3) & 3);

        const uint32_t tb = sbase + (s & 3) * BUF_B;
        #pragma unroll
        for (int kk = 0; kk < 2; kk++) {
            const uint32_t kx = kk ? 32u : 0u;
            uint32_t ah[4][4];
            #pragma unroll
            for (int mi = 0; mi < 4; mi++)
                ldsm_x4((tb + 0 * TILE_B + mi * 1024) + (aoff ^ kx),
                        ah[mi][0], ah[mi][1], ah[mi][2], ah[mi][3]);
            uint32_t bh[8][2];
            #pragma unroll
            for (int nb = 0; nb < 4; nb++)
                ldsm_x4((tb + 1 * TILE_B + nb * 1024) + (boff ^ kx),
                        bh[nb*2][0], bh[nb*2][1], bh[nb*2+1][0], bh[nb*2+1][1]);
            #pragma unroll
            for (int mi = 0; mi < 4; mi++)
                #pragma unroll
                for (int ni = 0; ni < 8; ni++)
                    mma16816h(acc[mi][ni], ah[mi], bh[ni]);
        }

        if (s + 3 < NSTEPS_)      { CPWAIT(2); }
        else if (s + 2 < NSTEPS_) { CPWAIT(1); }
        else if (s + 1 < NSTEPS_) { CPWAIT(0); }
        if (s + 1 < NSTEPS_) __syncthreads();
    }

    // ---- epilogue -----------------------------------------------------------
    #pragma unroll
    for (int mi = 0; mi < 4; mi++) {
        #pragma unroll
        for (int ni = 0; ni < 8; ni++) {
            const int cc = n0 + wn * 64 + ni * 8 + (lane & 3) * 2;
            const float b0v = bias[cc], b1v = bias[cc + 1];
            #pragma unroll
            for (int half = 0; half < 2; half++) {
                const int m = m0 + wm * 64 + mi * 16 + (lane >> 2) + half * 8;
                float v0 = acc[mi][ni][half * 2 + 0] + b0v;
                float v1 = acc[mi][ni][half * 2 + 1] + b1v;
                if (MODE == 0) {
                    const int bb = m >> 10, n = m & 1023;
                    const int trip = cc / D_;
                    const int rem = cc - trip * D_;
                    const int h = rem >> 6, d = rem & 63;
                    size_t off = ((((size_t)bb * H_ + h) * N_) + n) * HD_ + d;
                    const float sc = (trip == 0) ? SCLOG2E : 1.0f;
                    __half* dst = (trip == 0) ? g_qf : (trip == 1) ? g_kf : g_vf;
                    *(__half2*)(dst + off) = __floats2half2_rn(v0 * sc, v1 * sc);
                } else {
                    *(float2*)&Cout[(size_t)m * D_ + cc] = make_float2(v0, v1);
                }
            }
        }
    }
}

// ------------------------- HMMA flash attention, 128 threads / 64 Q-rows -----
// 3 CTAs/SM: co-resident CTAs hide each other's softmax MUFU windows.
#define ATT_Q_B   8192                  // Q: 64*128B
#define ATT_ST_B  16384                 // Kf + Vf: 2 * 64*128B
#define NSTAGE_A  4
#define SMEM_ATTN (ATT_Q_B + NSTAGE_A * ATT_ST_B)   // 72 KB

__global__ __launch_bounds__(128, 3)
void attn_mma()
{
    extern __shared__ __align__(1024) char sm[];
    const uint32_t sb = smem_u32(sm);
    const int tid = threadIdx.x, lane = tid & 31, wid = tid >> 5;
    const int bh = blockIdx.y, q0 = blockIdx.x * 64;
    const size_t bo = (size_t)bh * N_ * HD_;

    const __half* __restrict__ Qf = g_qf + bo + (size_t)q0 * HD_;
    const __half* __restrict__ Kf = g_kf + bo;
    const __half* __restrict__ Vf = g_vf + bo;

    // Q tile: 64 rows x 128 B = 512 chunks, 4/thread
    #pragma unroll
    for (int j = 0; j < 4; j++) {
        const int id = j * 128 + tid;
        const int r  = id >> 3;
        const int c  = id & 7;
        CP16(sb + SWZ128((uint32_t)(r * 128 + c * 16)), Qf + (size_t)r * HD_ + c * 8);
    }
    CPCOMMIT();

    auto load_kv = [&](int it, int st) {
        const int kt = it * 64;
        #pragma unroll
        for (int j = 0; j < 8; j++) {
            const int id = (j & 3) * 128 + tid;  // 0..511 within tile
            const int t  = j >> 2;               // 0:Kf 1:Vf
            const int r  = id >> 3;              // 0..63
            const int c  = id & 7;
            const __half* src = ((t == 0) ? Kf : Vf) + (size_t)(kt + r) * HD_ + c * 8;
            CP16(sb + ATT_Q_B + st * ATT_ST_B + t * 8192 +
                 SWZ128((uint32_t)(r * 128 + c * 16)), src);
        }
        CPCOMMIT();
    };
    load_kv(0, 0);
    load_kv(1, 1);
    load_kv(2, 2);

    CPWAIT(2);             // Q + KV0 ready
    __syncthreads();

    uint32_t qh[4][4];
    const int arow = wid * 16 + (lane & 15);
    #pragma unroll
    for (int kc = 0; kc < 4; kc++) {
        const uint32_t off = SWZ128((uint32_t)(arow * 128 + (kc * 2 + (lane >> 4)) * 16));
        ldsm_x4(sb + off, qh[kc][0], qh[kc][1], qh[kc][2], qh[kc][3]);
    }

    float o[8][4];
    #pragma unroll
    for (int i = 0; i < 8; i++)
        #pragma unroll
        for (int e = 0; e < 4; e++) o[i][e] = 0.0f;
    float m0r = -1e30f, m1r = -1e30f, l0r = 0.0f, l1r = 0.0f;

    const int krow = (lane & 7) + ((lane >> 4) & 1) * 8;
    const int kchk = (lane >> 3) & 1;
    const int vrow = lane & 15;
    const int vchk = lane >> 4;

    #pragma unroll 1
    for (int it = 0; it < 16; it++) {
        if (it + 3 < 16) load_kv(it + 3, (it + 3) & 3);

        const uint32_t kb = sb + ATT_Q_B + (it & 3) * ATT_ST_B;

        // ---- S = Q K^T (single-pass fp16) --------------------------------------
        float s[8][4];
        #pragma unroll
        for (int i = 0; i < 8; i++)
            #pragma unroll
            for (int e = 0; e < 4; e++) s[i][e] = 0.0f;

        #pragma unroll
        for (int kc = 0; kc < 4; kc++) {
            #pragma unroll
            for (int p = 0; p < 4; p++) {
                const uint32_t off =
                    SWZ128((uint32_t)((p * 16 + krow) * 128 + (kc * 2 + kchk) * 16));
                uint32_t h0, h1, h2, h3;
                ldsm_x4(kb + off, h0, h1, h2, h3);
                uint32_t bh0[2] = {h0, h1}, bh1[2] = {h2, h3};
                mma16816h(s[2*p],     qh[kc], bh0);
                mma16816h(s[2*p + 1], qh[kc], bh1);
            }
        }

        // ---- online softmax ---------------------------------------------------
        float t0 = -1e30f, t1 = -1e30f;
        #pragma unroll
        for (int nt = 0; nt < 8; nt++) {
            t0 = fmaxf(t0, fmaxf(s[nt][0], s[nt][1]));
            t1 = fmaxf(t1, fmaxf(s[nt][2], s[nt][3]));
        }
        t0 = fmaxf(t0, __shfl_xor_sync(0xffffffffu, t0, 1));
        t0 = fmaxf(t0, __shfl_xor_sync(0xffffffffu, t0, 2));
        t1 = fmaxf(t1, __shfl_xor_sync(0xffffffffu, t1, 1));
        t1 = fmaxf(t1, __shfl_xor_sync(0xffffffffu, t1, 2));
        const float mn0 = fmaxf(m0r, t0), mn1 = fmaxf(m1r, t1);
        const float cr0 = ex2f(m0r - mn0), cr1 = ex2f(m1r - mn1);
        m0r = mn0; m1r = mn1;
        l0r *= cr0; l1r *= cr1;
        #pragma unroll
        for (int nt = 0; nt < 8; nt++) {
            o[nt][0] *= cr0; o[nt][1] *= cr0;
            o[nt][2] *= cr1; o[nt][3] *= cr1;
        }
        float ps0 = 0.0f, ps1 = 0.0f;
        #pragma unroll
        for (int nt = 0; nt < 8; nt++) {
            s[nt][0] = ex2f(s[nt][0] - mn0);
            s[nt][1] = ex2f(s[nt][1] - mn0);
            s[nt][2] = ex2f(s[nt][2] - mn1);
            s[nt][3] = ex2f(s[nt][3] - mn1);
            ps0 += s[nt][0] + s[nt][1];
            ps1 += s[nt][2] + s[nt][3];
        }
        l0r += ps0; l1r += ps1;

        // ---- P -> fp16 A-fragments ----------------------------------------------
        uint32_t aph[4][4];
        #pragma unroll
        for (int kc = 0; kc < 4; kc++) {
            #pragma unroll
            for (int g = 0; g < 4; g++) {
                const int nt = 2 * kc + (g >> 1);
                aph[kc][g] = packhf(s[nt][(g & 1) * 2 + 0], s[nt][(g & 1) * 2 + 1]);
            }
        }

        // ---- O += P V (single-pass fp16) ----------------------------------------
        #pragma unroll
        for (int kc = 0; kc < 4; kc++) {
            #pragma unroll
            for (int pr = 0; pr < 4; pr++) {
                const uint32_t off =
                    SWZ128((uint32_t)((kc * 16 + vrow) * 128 + (pr * 2 + vchk) * 16));
                uint32_t h0, h1, h2, h3;
                ldsm_x4t(kb + 8192 + off, h0, h1, h2, h3);
                uint32_t vh0[2] = {h0, h1}, vh1[2] = {h2, h3};
                mma16816h(o[2*pr],     aph[kc], vh0);
                mma16816h(o[2*pr + 1], aph[kc], vh1);
            }
        }

        if (it + 3 < 16)      { CPWAIT(2); }
        else if (it + 2 < 16) { CPWAIT(1); }
        else if (it + 1 < 16) { CPWAIT(0); }
        if (it + 1 < 16) __syncthreads();
    }

    // ---- finalize: write fp16 ctx directly ------------------------------------
    l0r += __shfl_xor_sync(0xffffffffu, l0r, 1);
    l0r += __shfl_xor_sync(0xffffffffu, l0r, 2);
    l1r += __shfl_xor_sync(0xffffffffu, l1r, 1);
    l1r += __shfl_xor_sync(0xffffffffu, l1r, 2);
    const float inv0 = 1.0f / l0r, inv1 = 1.0f / l1r;

    const int b = bh / H_, h = bh - b * H_;
    const int row0 = q0 + wid * 16 + (lane >> 2);
    __half* out0 = g_cf + ((size_t)(b * N_ + row0)) * D_ + h * HD_ + (lane & 3) * 2;
    __half* out1 = out0 + (size_t)8 * D_;
    #pragma unroll
    for (int nt = 0; nt < 8; nt++) {
        *(__half2*)(out0 + nt * 8) = __floats2half2_rn(o[nt][0] * inv0, o[nt][1] * inv0);
        *(__half2*)(out1 + nt * 8) = __floats2half2_rn(o[nt][2] * inv1, o[nt][3] * inv1);
    }
}

// ---------------------------------------------------------------------------
extern "C" void kernel_launch(void* const* d_in, const int* in_sizes, int n_in,
                              void* d_out, int out_size)
{
    const float* x     = (const float*)d_in[0];
    const float* Wqkv  = (const float*)d_in[1];
    const float* bqkv  = (const float*)d_in[2];
    const float* Wproj = (const float*)d_in[3];
    const float* bproj = (const float*)d_in[4];
    float* out = (float*)d_out;

    cudaFuncSetAttribute(mma_gemm<0>, cudaFuncAttributeMaxDynamicSharedMemorySize, SMEM_GEMM);
    cudaFuncSetAttribute(mma_gemm<1>, cudaFuncAttributeMaxDynamicSharedMemorySize, SMEM_GEMM);
    cudaFuncSetAttribute(attn_mma,    cudaFuncAttributeMaxDynamicSharedMemorySize, SMEM_ATTN);

    cvt_x_kernel<<<(M_ * D_ / 4 + 255) / 256, 256>>>(x);
    cvtT_kernel<0><<<dim3(C3_ / 32, D_ / 32), dim3(32, 8)>>>(Wqkv);
    cvtT_kernel<1><<<dim3(D_ / 32, D_ / 32), dim3(32, 8)>>>(Wproj);

    // QKV GEMM (R9 config) -> Q (pre-scaled), K, V fp16
    mma_gemm<0><<<dim3(C3_ / 128, M_ / 128), 128, SMEM_GEMM>>>(bqkv, nullptr);

    // flash attention: 64 Q-rows/CTA, 3 CTAs/SM
    attn_mma<<<dim3(N_ / 64, B_ * H_), 128, SMEM_ATTN>>>();

    // output projection (R9 config)
    mma_gemm<1><<<dim3(D_ / 128, M_ / 128), 128, SMEM_GEMM>>>(bproj, out);
}

// round 13
// speedup vs baseline: 1.3527x; 1.0629x over previous
#include <cuda_runtime.h>
#include <cuda_fp16.h>
#include <cstdint>

#define B_  8
#define N_  1024
#define D_  768
#define H_  12
#define HD_ 64
#define M_  (B_*N_)      // 8192
#define C3_ (3*D_)       // 2304
#define SCLOG2E 0.1803368801111204f   // 0.125 * log2(e)

// ------------------------- scratch (__device__ globals) --------------------
__device__ __half g_cf[(size_t)M_*D_];           // attention output (fp16)

__device__ __half g_qf[(size_t)B_*H_*N_*HD_];    // Q fp16 (pre-scaled)
__device__ __half g_kf[(size_t)B_*H_*N_*HD_];    // K fp16
__device__ __half g_vf[(size_t)B_*H_*N_*HD_];    // V fp16

__device__ __half g_xf[(size_t)M_*D_];           // x   (fp16)
__device__ __half g_wf[(size_t)C3_*D_];          // W_qkv^T  [2304][768] fp16
__device__ __half g_wpf[(size_t)D_*D_];          // W_proj^T [768][768]  fp16

// ------------------------- helpers -----------------------------------------
__device__ __forceinline__ uint32_t smem_u32(const void* p) {
    uint32_t a;
    asm("{ .reg .u64 t; cvta.to.shared.u64 t, %1; cvt.u32.u64 %0, t; }"
        : "=r"(a) : "l"(p));
    return a;
}
#define SWZ128(o) ((o) ^ (((o) >> 3) & 0x70))

#define CP16(s, g)  asm volatile("cp.async.cg.shared.global [%0], [%1], 16;" :: "r"(s), "l"(g))
#define CPCOMMIT()  asm volatile("cp.async.commit_group;" ::: "memory")
#define CPWAIT(n)   asm volatile("cp.async.wait_group %0;" :: "n"(n) : "memory")

__device__ __forceinline__ void ldsm_x4(uint32_t addr, uint32_t& r0, uint32_t& r1,
                                        uint32_t& r2, uint32_t& r3) {
    asm volatile("ldmatrix.sync.aligned.m8n8.x4.shared.b16 {%0,%1,%2,%3}, [%4];"
                 : "=r"(r0), "=r"(r1), "=r"(r2), "=r"(r3) : "r"(addr));
}
__device__ __forceinline__ void ldsm_x4t(uint32_t addr, uint32_t& r0, uint32_t& r1,
                                         uint32_t& r2, uint32_t& r3) {
    asm volatile("ldmatrix.sync.aligned.m8n8.x4.trans.shared.b16 {%0,%1,%2,%3}, [%4];"
                 : "=r"(r0), "=r"(r1), "=r"(r2), "=r"(r3) : "r"(addr));
}
__device__ __forceinline__ void mma16816h(float* d, const uint32_t* a, const uint32_t* b) {
    asm volatile(
        "mma.sync.aligned.m16n8k16.row.col.f32.f16.f16.f32 "
        "{%0,%1,%2,%3}, {%4,%5,%6,%7}, {%8,%9}, {%0,%1,%2,%3};"
        : "+f"(d[0]), "+f"(d[1]), "+f"(d[2]), "+f"(d[3])
        : "r"(a[0]), "r"(a[1]), "r"(a[2]), "r"(a[3]), "r"(b[0]), "r"(b[1]));
}
__device__ __forceinline__ float ex2f(float x) {
    float y;
    asm("ex2.approx.f32 %0, %1;" : "=f"(y) : "f"(x));
    return y;
}
__device__ __forceinline__ uint32_t packhf(float lo, float hi) {
    uint32_t r;
    asm("cvt.rn.f16x2.f32 %0, %1, %2;" : "=r"(r) : "f"(hi), "f"(lo));
    return r;
}

// ------------------------- fused prep: cvt_x + W transposes -----------------
#define NB_X   (M_ * D_ / 1024)                       // 6144 blocks, 256 f4 each
#define NB_W0  ((C3_ / 32) * (D_ / 32))               // 1728
#define NB_W1  ((D_ / 32) * (D_ / 32))                // 576
#define NB_ALL (NB_X + NB_W0 + NB_W1)

__global__ void prep_kernel(const float* __restrict__ x,
                            const float* __restrict__ Wqkv,
                            const float* __restrict__ Wproj)
{
    __shared__ float tile[32][33];
    const int bx = blockIdx.x, tid = threadIdx.x;

    if (bx < NB_X) {
        const int i = bx * 256 + tid;                  // float4 index
        float4 v = ((const float4*)x)[i];
        ((__half2*)g_xf)[i * 2]     = __floats2half2_rn(v.x, v.y);
        ((__half2*)g_xf)[i * 2 + 1] = __floats2half2_rn(v.z, v.w);
        return;
    }

    const int tx = tid & 31, ty = tid >> 5;            // 32 x 8
    const float* W;
    __half* dst;
    int nb, kb, Nn;
    if (bx < NB_X + NB_W0) {
        const int b = bx - NB_X;
        W = Wqkv; dst = g_wf; Nn = C3_;
        nb = (b % (C3_ / 32)) * 32;
        kb = (b / (C3_ / 32)) * 32;
    } else {
        const int b = bx - NB_X - NB_W0;
        W = Wproj; dst = g_wpf; Nn = D_;
        nb = (b % (D_ / 32)) * 32;
        kb = (b / (D_ / 32)) * 32;
    }
    #pragma unroll
    for (int r = ty; r < 32; r += 8)
        tile[r][tx] = W[(size_t)(kb + r) * Nn + nb + tx];
    __syncthreads();
    #pragma unroll
    for (int r = ty; r < 32; r += 8) {
        const int n = nb + r, k = kb + tx;
        dst[(size_t)n * D_ + k] = __float2half_rn(tile[tx][r]);
    }
}

// ------------------------- fp16 HMMA GEMM, KSTEP=64, 3-stage -----------------
#define KSTEP_    64
#define NSTEPS_   (D_ / KSTEP_)    // 12
#define TILE_B    16384            // 128 rows * 128 bytes (fp16 128x64)
#define BUF_B     (2 * TILE_B)     // A, B  (32 KB / stage)
#define NSTAGE_G  3
#define SMEM_GEMM (NSTAGE_G * BUF_B)   // 96 KB

template<int MODE>
__global__ __launch_bounds__(128, 2)
void mma_gemm(const float* __restrict__ bias, float* __restrict__ Cout)
{
    extern __shared__ __align__(1024) char smem[];
    const int tid = threadIdx.x, lane = tid & 31, wid = tid >> 5;
    const int m0 = blockIdx.y * 128, n0 = blockIdx.x * 128;
    const int wm = wid & 1;        // 0..1 -> 64 M-rows
    const int wn = wid >> 1;       // 0..1 -> 64 N-cols

    const __half* __restrict__ Af = (MODE == 0) ? g_xf : g_cf;
    const __half* __restrict__ Bf = (MODE == 0) ? g_wf : g_wpf;

    // load mapping: per tile 1024 16B-chunks, 128 threads x 8
    const uint32_t sbase = smem_u32(smem);

    const uint32_t aoff = SWZ128((uint32_t)((wm * 64 + (lane & 15)) * 128 + (lane >> 4) * 16));
    const uint32_t boff = SWZ128((uint32_t)((wn * 64 + (lane & 7) + ((lane & 16) ? 8 : 0)) * 128
                                            + ((lane >> 3) & 1) * 16));

    float acc[4][8][4];
    #pragma unroll
    for (int i = 0; i < 4; i++)
        #pragma unroll
        for (int j = 0; j < 8; j++)
            #pragma unroll
            for (int e = 0; e < 4; e++) acc[i][j][e] = 0.0f;

    auto load_step = [&](int s, int st) {
        const int kt = s * KSTEP_;
        const uint32_t d = sbase + st * BUF_B;
        #pragma unroll
        for (int j = 0; j < 8; j++) {
            const int id = j * 128 + tid;
            const int r  = id >> 3;
            const int c  = id & 7;
            const uint32_t so = SWZ128((uint32_t)(r * 128 + c * 16));
            CP16(d + so,          Af + (size_t)(m0 + r) * D_ + kt + c * 8);
            CP16(d + TILE_B + so, Bf + (size_t)(n0 + r) * D_ + kt + c * 8);
        }
        CPCOMMIT();
    };

    load_step(0, 0);
    load_step(1, 1);
    CPWAIT(1);               // stage 0 ready
    __syncthreads();

    #pragma unroll 1
    for (int s = 0; s < NSTEPS_; s++) {
        if (s + 2 < NSTEPS_) load_step(s + 2, (s + 2) % 3);

        const uint32_t tb = sbase + (s % 3) * BUF_B;
        #pragma unroll
        for (int kk = 0; kk < 4; kk++) {
            const uint32_t kx = (uint32_t)(kk * 32);
            uint32_t ah[4][4];
            #pragma unroll
            for (int mi = 0; mi < 4; mi++)
                ldsm_x4((tb + mi * 2048) + (aoff ^ kx),
                        ah[mi][0], ah[mi][1], ah[mi][2], ah[mi][3]);
            uint32_t bh[8][2];
            #pragma unroll
            for (int nb = 0; nb < 4; nb++)
                ldsm_x4((tb + TILE_B + nb * 2048) + (boff ^ kx),
                        bh[nb*2][0], bh[nb*2][1], bh[nb*2+1][0], bh[nb*2+1][1]);
            #pragma unroll
            for (int mi = 0; mi < 4; mi++)
                #pragma unroll
                for (int ni = 0; ni < 8; ni++)
                    mma16816h(acc[mi][ni], ah[mi], bh[ni]);
        }

        if (s + 2 < NSTEPS_)      { CPWAIT(1); }
        else if (s + 1 < NSTEPS_) { CPWAIT(0); }
        if (s + 1 < NSTEPS_) __syncthreads();
    }

    // ---- epilogue -----------------------------------------------------------
    #pragma unroll
    for (int mi = 0; mi < 4; mi++) {
        #pragma unroll
        for (int ni = 0; ni < 8; ni++) {
            const int cc = n0 + wn * 64 + ni * 8 + (lane & 3) * 2;
            const float b0v = bias[cc], b1v = bias[cc + 1];
            #pragma unroll
            for (int half = 0; half < 2; half++) {
                const int m = m0 + wm * 64 + mi * 16 + (lane >> 2) + half * 8;
                float v0 = acc[mi][ni][half * 2 + 0] + b0v;
                float v1 = acc[mi][ni][half * 2 + 1] + b1v;
                if (MODE == 0) {
                    const int bb = m >> 10, n = m & 1023;
                    const int trip = cc / D_;
                    const int rem = cc - trip * D_;
                    const int h = rem >> 6, d = rem & 63;
                    size_t off = ((((size_t)bb * H_ + h) * N_) + n) * HD_ + d;
                    const float sc = (trip == 0) ? SCLOG2E : 1.0f;
                    __half* dst = (trip == 0) ? g_qf : (trip == 1) ? g_kf : g_vf;
                    *(__half2*)(dst + off) = __floats2half2_rn(v0 * sc, v1 * sc);
                } else {
                    *(float2*)&Cout[(size_t)m * D_ + cc] = make_float2(v0, v1);
                }
            }
        }
    }
}

// ------------------------- HMMA flash attention (R12) ------------------------
#define ATT_Q_B   8192                  // Q: 64*128B
#define ATT_ST_B  16384                 // Kf + Vf: 2 * 64*128B
#define NSTAGE_A  4
#define SMEM_ATTN (ATT_Q_B + NSTAGE_A * ATT_ST_B)   // 72 KB

__global__ __launch_bounds__(128, 3)
void attn_mma()
{
    extern __shared__ __align__(1024) char sm[];
    const uint32_t sb = smem_u32(sm);
    const int tid = threadIdx.x, lane = tid & 31, wid = tid >> 5;
    const int bh = blockIdx.y, q0 = blockIdx.x * 64;
    const size_t bo = (size_t)bh * N_ * HD_;

    const __half* __restrict__ Qf = g_qf + bo + (size_t)q0 * HD_;
    const __half* __restrict__ Kf = g_kf + bo;
    const __half* __restrict__ Vf = g_vf + bo;

    // Q tile: 64 rows x 128 B = 512 chunks, 4/thread
    #pragma unroll
    for (int j = 0; j < 4; j++) {
        const int id = j * 128 + tid;
        const int r  = id >> 3;
        const int c  = id & 7;
        CP16(sb + SWZ128((uint32_t)(r * 128 + c * 16)), Qf + (size_t)r * HD_ + c * 8);
    }
    CPCOMMIT();

    auto load_kv = [&](int it, int st) {
        const int kt = it * 64;
        #pragma unroll
        for (int j = 0; j < 8; j++) {
            const int id = (j & 3) * 128 + tid;
            const int t  = j >> 2;               // 0:Kf 1:Vf
            const int r  = id >> 3;
            const int c  = id & 7;
            const __half* src = ((t == 0) ? Kf : Vf) + (size_t)(kt + r) * HD_ + c * 8;
            CP16(sb + ATT_Q_B + st * ATT_ST_B + t * 8192 +
                 SWZ128((uint32_t)(r * 128 + c * 16)), src);
        }
        CPCOMMIT();
    };
    load_kv(0, 0);
    load_kv(1, 1);
    load_kv(2, 2);

    CPWAIT(2);             // Q + KV0 ready
    __syncthreads();

    uint32_t qh[4][4];
    const int arow = wid * 16 + (lane & 15);
    #pragma unroll
    for (int kc = 0; kc < 4; kc++) {
        const uint32_t off = SWZ128((uint32_t)(arow * 128 + (kc * 2 + (lane >> 4)) * 16));
        ldsm_x4(sb + off, qh[kc][0], qh[kc][1], qh[kc][2], qh[kc][3]);
    }

    float o[8][4];
    #pragma unroll
    for (int i = 0; i < 8; i++)
        #pragma unroll
        for (int e = 0; e < 4; e++) o[i][e] = 0.0f;
    float m0r = -1e30f, m1r = -1e30f, l0r = 0.0f, l1r = 0.0f;

    const int krow = (lane & 7) + ((lane >> 4) & 1) * 8;
    const int kchk = (lane >> 3) & 1;
    const int vrow = lane & 15;
    const int vchk = lane >> 4;

    #pragma unroll 1
    for (int it = 0; it < 16; it++) {
        if (it + 3 < 16) load_kv(it + 3, (it + 3) & 3);

        const uint32_t kb = sb + ATT_Q_B + (it & 3) * ATT_ST_B;

        // ---- S = Q K^T (single-pass fp16) --------------------------------------
        float s[8][4];
        #pragma unroll
        for (int i = 0; i < 8; i++)
            #pragma unroll
            for (int e = 0; e < 4; e++) s[i][e] = 0.0f;

        #pragma unroll
        for (int kc = 0; kc < 4; kc++) {
            #pragma unroll
            for (int p = 0; p < 4; p++) {
                const uint32_t off =
                    SWZ128((uint32_t)((p * 16 + krow) * 128 + (kc * 2 + kchk) * 16));
                uint32_t h0, h1, h2, h3;
                ldsm_x4(kb + off, h0, h1, h2, h3);
                uint32_t bh0[2] = {h0, h1}, bh1[2] = {h2, h3};
                mma16816h(s[2*p],     qh[kc], bh0);
                mma16816h(s[2*p + 1], qh[kc], bh1);
            }
        }

        // ---- online softmax ---------------------------------------------------
        float t0 = -1e30f, t1 = -1e30f;
        #pragma unroll
        for (int nt = 0; nt < 8; nt++) {
            t0 = fmaxf(t0, fmaxf(s[nt][0], s[nt][1]));
            t1 = fmaxf(t1, fmaxf(s[nt][2], s[nt][3]));
        }
        t0 = fmaxf(t0, __shfl_xor_sync(0xffffffffu, t0, 1));
        t0 = fmaxf(t0, __shfl_xor_sync(0xffffffffu, t0, 2));
        t1 = fmaxf(t1, __shfl_xor_sync(0xffffffffu, t1, 1));
        t1 = fmaxf(t1, __shfl_xor_sync(0xffffffffu, t1, 2));
        const float mn0 = fmaxf(m0r, t0), mn1 = fmaxf(m1r, t1);
        const float cr0 = ex2f(m0r - mn0), cr1 = ex2f(m1r - mn1);
        m0r = mn0; m1r = mn1;
        l0r *= cr0; l1r *= cr1;
        #pragma unroll
        for (int nt = 0; nt < 8; nt++) {
            o[nt][0] *= cr0; o[nt][1] *= cr0;
            o[nt][2] *= cr1; o[nt][3] *= cr1;
        }
        float ps0 = 0.0f, ps1 = 0.0f;
        #pragma unroll
        for (int nt = 0; nt < 8; nt++) {
            s[nt][0] = ex2f(s[nt][0] - mn0);
            s[nt][1] = ex2f(s[nt][1] - mn0);
            s[nt][2] = ex2f(s[nt][2] - mn1);
            s[nt][3] = ex2f(s[nt][3] - mn1);
            ps0 += s[nt][0] + s[nt][1];
            ps1 += s[nt][2] + s[nt][3];
        }
        l0r += ps0; l1r += ps1;

        // ---- P -> fp16 A-fragments ----------------------------------------------
        uint32_t aph[4][4];
        #pragma unroll
        for (int kc = 0; kc < 4; kc++) {
            #pragma unroll
            for (int g = 0; g < 4; g++) {
                const int nt = 2 * kc + (g >> 1);
                aph[kc][g] = packhf(s[nt][(g & 1) * 2 + 0], s[nt][(g & 1) * 2 + 1]);
            }
        }

        // ---- O += P V (single-pass fp16) ----------------------------------------
        #pragma unroll
        for (int kc = 0; kc < 4; kc++) {
            #pragma unroll
            for (int pr = 0; pr < 4; pr++) {
                const uint32_t off =
                    SWZ128((uint32_t)((kc * 16 + vrow) * 128 + (pr * 2 + vchk) * 16));
                uint32_t h0, h1, h2, h3;
                ldsm_x4t(kb + 8192 + off, h0, h1, h2, h3);
                uint32_t vh0[2] = {h0, h1}, vh1[2] = {h2, h3};
                mma16816h(o[2*pr],     aph[kc], vh0);
                mma16816h(o[2*pr + 1], aph[kc], vh1);
            }
        }

        if (it + 3 < 16)      { CPWAIT(2); }
        else if (it + 2 < 16) { CPWAIT(1); }
        else if (it + 1 < 16) { CPWAIT(0); }
        if (it + 1 < 16) __syncthreads();
    }

    // ---- finalize: write fp16 ctx directly ------------------------------------
    l0r += __shfl_xor_sync(0xffffffffu, l0r, 1);
    l0r += __shfl_xor_sync(0xffffffffu, l0r, 2);
    l1r += __shfl_xor_sync(0xffffffffu, l1r, 1);
    l1r += __shfl_xor_sync(0xffffffffu, l1r, 2);
    const float inv0 = 1.0f / l0r, inv1 = 1.0f / l1r;

    const int b = bh / H_, h = bh - b * H_;
    const int row0 = q0 + wid * 16 + (lane >> 2);
    __half* out0 = g_cf + ((size_t)(b * N_ + row0)) * D_ + h * HD_ + (lane & 3) * 2;
    __half* out1 = out0 + (size_t)8 * D_;
    #pragma unroll
    for (int nt = 0; nt < 8; nt++) {
        *(__half2*)(out0 + nt * 8) = __floats2half2_rn(o[nt][0] * inv0, o[nt][1] * inv0);
        *(__half2*)(out1 + nt * 8) = __floats2half2_rn(o[nt][2] * inv1, o[nt][3] * inv1);
    }
}

// ---------------------------------------------------------------------------
extern "C" void kernel_launch(void* const* d_in, const int* in_sizes, int n_in,
                              void* d_out, int out_size)
{
    const float* x     = (const float*)d_in[0];
    const float* Wqkv  = (const float*)d_in[1];
    const float* bqkv  = (const float*)d_in[2];
    const float* Wproj = (const float*)d_in[3];
    const float* bproj = (const float*)d_in[4];
    float* out = (float*)d_out;

    cudaFuncSetAttribute(mma_gemm<0>, cudaFuncAttributeMaxDynamicSharedMemorySize, SMEM_GEMM);
    cudaFuncSetAttribute(mma_gemm<1>, cudaFuncAttributeMaxDynamicSharedMemorySize, SMEM_GEMM);
    cudaFuncSetAttribute(attn_mma,    cudaFuncAttributeMaxDynamicSharedMemorySize, SMEM_ATTN);

    // fused conversions (x -> fp16, W transposes -> fp16)
    prep_kernel<<<NB_ALL, 256>>>(x, Wqkv, Wproj);

    // QKV GEMM (KSTEP=64, 3-stage) -> Q (pre-scaled), K, V fp16
    mma_gemm<0><<<dim3(C3_ / 128, M_ / 128), 128, SMEM_GEMM>>>(bqkv, nullptr);

    // flash attention: 64 Q-rows/CTA, 3 CTAs/SM
    attn_mma<<<dim3(N_ / 64, B_ * H_), 128, SMEM_ATTN>>>();

    // output projection
    mma_gemm<1><<<dim3(D_ / 128, M_ / 128), 128, SMEM_GEMM>>>(bproj, out);
}